// round 1
// baseline (speedup 1.0000x reference)
#include <cuda_runtime.h>
#include <cuda_bf16.h>
#include <math.h>

// ---------------------------------------------------------------------------
// GRU (Keras reset_after=True):  B=32, T=1024, D=1024, H=1024
//   x_proj = input @ kernel + b_in                       (kernel A, one GEMM)
//   per t:  rec = h @ U + b_rec; gates; h' = z*h+(1-z)*hh (kernel B, persistent)
// Output: outputs [B,T,H] then h_last [B,H] appended.
// ---------------------------------------------------------------------------

#define BB 32
#define TT 1024
#define DD 1024
#define HH 1024
#define H3 3072

// 402 MB scratch for x_proj (allowed: __device__ global array)
__device__ float g_xproj[(size_t)BB * TT * H3];

// grid barrier state (reset by last-exiting CTA so graph replays start clean)
__device__ unsigned g_arrive = 0;
__device__ unsigned g_exit   = 0;

// ------------------------------ f32x2 helpers ------------------------------
__device__ __forceinline__ unsigned smaddr(const void* p) {
    return (unsigned)__cvta_generic_to_shared(p);
}
__device__ __forceinline__ unsigned long long bcast2(float x) {
    unsigned long long r;
    asm("mov.b64 %0, {%1, %1};" : "=l"(r) : "f"(x));
    return r;
}
__device__ __forceinline__ void ffma2(unsigned long long& d, unsigned long long a,
                                      unsigned long long b) {
    asm volatile("fma.rn.f32x2 %0, %1, %2, %0;" : "+l"(d) : "l"(a), "l"(b));
}
__device__ __forceinline__ void lds_v2b64(unsigned long long& a, unsigned long long& b,
                                          unsigned addr) {
    asm volatile("ld.shared.v2.b64 {%0, %1}, [%2];" : "=l"(a), "=l"(b) : "r"(addr));
}
__device__ __forceinline__ void sts_v2b64(unsigned addr, unsigned long long a,
                                          unsigned long long b) {
    asm volatile("st.shared.v2.b64 [%0], {%1, %2};" :: "r"(addr), "l"(a), "l"(b)
                 : "memory");
}
__device__ __forceinline__ float2 unpack2(unsigned long long v) {
    float2 r;
    asm("mov.b64 {%0, %1}, %2;" : "=f"(r.x), "=f"(r.y) : "l"(v));
    return r;
}

// ---------------------------------------------------------------------------
// Kernel A: x_proj = input[BT,D] @ W[D,3H] + b_in.  Tile 128x128x16, 8x8/thread.
// ---------------------------------------------------------------------------
#define A_BM 128
#define A_BN 128
#define A_BK 16

__global__ void __launch_bounds__(256) xproj_kernel(
    const float* __restrict__ A,   // [BT, D]
    const float* __restrict__ W,   // [D, 3H]
    const float* __restrict__ bias // [2, 3H] (row 0 = b_in)
) {
    __shared__ float As[A_BK][A_BM];
    __shared__ float Ws[A_BK][A_BN];

    const int tid = threadIdx.x;
    const int bn  = blockIdx.x % (H3 / A_BN);
    const int bm  = blockIdx.x / (H3 / A_BN);

    const int tx = tid & 15;     // n group
    const int ty = tid >> 4;     // m group
    const int m0 = ty * 8;
    const int n0 = tx * 8;

    unsigned long long acc[8][4];
#pragma unroll
    for (int i = 0; i < 8; i++)
#pragma unroll
        for (int j = 0; j < 4; j++) acc[i][j] = 0ull;

    const unsigned ws_base = smaddr(&Ws[0][0]);

    for (int k0 = 0; k0 < DD; k0 += A_BK) {
        // load A tile (transpose into As[k][m])
#pragma unroll
        for (int rep = 0; rep < 2; rep++) {
            int idx = tid + rep * 256;
            int row = idx >> 2;
            int q   = idx & 3;
            float4 v = *(const float4*)&A[(size_t)(bm * A_BM + row) * DD + k0 + q * 4];
            As[q * 4 + 0][row] = v.x;
            As[q * 4 + 1][row] = v.y;
            As[q * 4 + 2][row] = v.z;
            As[q * 4 + 3][row] = v.w;
        }
        // load W tile
#pragma unroll
        for (int rep = 0; rep < 2; rep++) {
            int idx  = tid + rep * 256;
            int krow = idx >> 5;
            int nq   = idx & 31;
            *(float4*)&Ws[krow][nq * 4] =
                *(const float4*)&W[(size_t)(k0 + krow) * H3 + bn * A_BN + nq * 4];
        }
        __syncthreads();

#pragma unroll
        for (int kk = 0; kk < A_BK; kk++) {
            float4 a0 = *(const float4*)&As[kk][m0];
            float4 a1 = *(const float4*)&As[kk][m0 + 4];
            unsigned long long a2[8];
            a2[0] = bcast2(a0.x); a2[1] = bcast2(a0.y);
            a2[2] = bcast2(a0.z); a2[3] = bcast2(a0.w);
            a2[4] = bcast2(a1.x); a2[5] = bcast2(a1.y);
            a2[6] = bcast2(a1.z); a2[7] = bcast2(a1.w);
            unsigned long long w0, w1, w2, w3;
            unsigned wa = ws_base + (unsigned)(kk * A_BN + n0) * 4u;
            lds_v2b64(w0, w1, wa);
            lds_v2b64(w2, w3, wa + 16);
#pragma unroll
            for (int i = 0; i < 8; i++) {
                ffma2(acc[i][0], a2[i], w0);
                ffma2(acc[i][1], a2[i], w1);
                ffma2(acc[i][2], a2[i], w2);
                ffma2(acc[i][3], a2[i], w3);
            }
        }
        __syncthreads();
    }

    // epilogue: + b_in, store
    float bv[8];
#pragma unroll
    for (int j = 0; j < 8; j++) bv[j] = __ldg(&bias[bn * A_BN + n0 + j]);

#pragma unroll
    for (int i = 0; i < 8; i++) {
        size_t row = (size_t)(bm * A_BM + m0 + i);
        float* dst = &g_xproj[row * H3 + bn * A_BN + n0];
        float2 p0 = unpack2(acc[i][0]);
        float2 p1 = unpack2(acc[i][1]);
        float2 p2 = unpack2(acc[i][2]);
        float2 p3 = unpack2(acc[i][3]);
        float4 o0 = make_float4(p0.x + bv[0], p0.y + bv[1], p1.x + bv[2], p1.y + bv[3]);
        float4 o1 = make_float4(p2.x + bv[4], p2.y + bv[5], p3.x + bv[6], p3.y + bv[7]);
        *(float4*)&dst[0] = o0;
        *(float4*)&dst[4] = o1;
    }
}

// ---------------------------------------------------------------------------
// Kernel B: persistent GRU recurrence.
// 128 CTAs x 256 threads. CTA c owns j-units [c*8, c*8+8) i.e. 24 GEMM columns
// (z|r|h slices). U slice lives in smem for the whole kernel; h staged per step.
// h state is read from / written to the output buffer itself (__ldcg/__stcg).
// ---------------------------------------------------------------------------
#define NCTA 128
#define JB 8                        // j-units per CTA
#define NCOL (3 * JB)               // 24 gemm cols per CTA
#define SM_H_FLOATS (HH * BB)       // 32768  (h_s[k][32], xor-swizzled)
#define SM_U_FLOATS (HH * NCOL)     // 24576  (U_s[k][24])
#define SMEM_BYTES ((SM_H_FLOATS + SM_U_FLOATS) * 4)

__global__ void __launch_bounds__(256, 1) gru_kernel(
    const float* __restrict__ U,    // [H, 3H]
    const float* __restrict__ bias, // [2, 3H] (row 1 = b_rec)
    float* __restrict__ out,        // [B, T, H]
    float* __restrict__ hlast,      // [B, H] or null
    int write_hlast
) {
    extern __shared__ float smem[];
    float* h_s = smem;                 // [1024][32] swizzled: h_s[k*32 + (b ^ (k&31))]
    float* U_s = smem + SM_H_FLOATS;   // [1024][24]

    const int tid  = threadIdx.x;
    const int j0   = blockIdx.x * JB;
    const int lane = tid & 31;
    const int warp = tid >> 5;

    // ---- one-time U slice load (stays resident in smem across all steps) ----
    for (int idx = tid; idx < SM_U_FLOATS; idx += 256) {
        int k = idx / NCOL;
        int m = idx % NCOL;
        int g = m >> 3;
        int jj = m & 7;
        U_s[idx] = __ldg(&U[(size_t)k * H3 + g * HH + j0 + jj]);
    }

    // gate-phase identity
    const int gb  = tid & 31;          // batch
    const int gjj = tid >> 5;          // 0..7
    const int jloc = j0 + gjj;
    const float brz = __ldg(&bias[H3 + jloc]);
    const float brr = __ldg(&bias[H3 + HH + jloc]);
    const float brh = __ldg(&bias[H3 + 2 * HH + jloc]);

    // gemm-phase identity: warp -> (colgroup, ksplit); lane = batch
    const int cg = warp & 1;           // 0/1 -> cols [0,12) / [12,24)
    const int ks = warp >> 1;          // 0..3 -> k quarter
    const int cb = cg * 12;
    const int lane4 = lane << 2;

    const unsigned h_base = smaddr(h_s);
    const unsigned u_base = smaddr(U_s);

    // staging identity: warp owns 4 batch rows, 8 k-segments per lane
    const int sb  = warp * 4 + (lane >> 3);   // batch row
    const int seg = lane & 7;

    for (int t = 0; t < TT; t++) {
        // ---- stage h_prev into swizzled smem (zeros at t==0) ----
        if (t == 0) {
#pragma unroll 4
            for (int i = 0; i < 32; i++) {
                int k = i * 32 + seg * 4;
#pragma unroll
                for (int j = 0; j < 4; j++) {
                    int kj = k + j;
                    h_s[kj * 32 + (sb ^ (kj & 31))] = 0.0f;
                }
            }
        } else {
            const float4* src =
                (const float4*)(out + ((size_t)sb * TT + (t - 1)) * HH);
#pragma unroll 4
            for (int i = 0; i < 32; i++) {
                int k = i * 32 + seg * 4;
                float4 v = __ldcg(&src[k >> 2]);
                h_s[(k + 0) * 32 + (sb ^ ((k + 0) & 31))] = v.x;
                h_s[(k + 1) * 32 + (sb ^ ((k + 1) & 31))] = v.y;
                h_s[(k + 2) * 32 + (sb ^ ((k + 2) & 31))] = v.z;
                h_s[(k + 3) * 32 + (sb ^ ((k + 3) & 31))] = v.w;
            }
        }

        // prefetch x_proj for the gate phase (long-latency DRAM, hide behind GEMM)
        const size_t xrow = ((size_t)gb * TT + t) * H3;
        const float xz = __ldg(&g_xproj[xrow + jloc]);
        const float xr = __ldg(&g_xproj[xrow + HH + jloc]);
        const float xh = __ldg(&g_xproj[xrow + 2 * HH + jloc]);

        __syncthreads();

        // ---- GEMM: rec[b=lane][cols cb..cb+11] over k quarter ----
        unsigned long long acc[6];
#pragma unroll
        for (int i = 0; i < 6; i++) acc[i] = 0ull;

        unsigned hrow = h_base + (unsigned)(ks * 256) * 128u;
        unsigned urow = u_base + ((unsigned)(ks * 256) * NCOL + cb) * 4u;

        for (int kb = 0; kb < 8; kb++) {
#pragma unroll
            for (int kk = 0; kk < 32; kk++) {
                float hv;
                unsigned ha = hrow + (unsigned)(kk * 128) + (unsigned)(lane4 ^ (kk << 2));
                asm volatile("ld.shared.f32 %0, [%1];" : "=f"(hv) : "r"(ha));
                unsigned long long h2 = bcast2(hv);
                unsigned long long w0, w1, w2, w3, w4, w5;
                unsigned ua = urow + (unsigned)(kk * (NCOL * 4));
                lds_v2b64(w0, w1, ua);
                lds_v2b64(w2, w3, ua + 16);
                lds_v2b64(w4, w5, ua + 32);
                ffma2(acc[0], h2, w0);
                ffma2(acc[1], h2, w1);
                ffma2(acc[2], h2, w2);
                ffma2(acc[3], h2, w3);
                ffma2(acc[4], h2, w4);
                ffma2(acc[5], h2, w5);
            }
            hrow += 32 * 128;
            urow += 32 * (NCOL * 4);
        }

        // h_prev for this thread's gate output (must read before h_s is reused)
        const float hp = h_s[jloc * 32 + (gb ^ (jloc & 31))];

        __syncthreads();   // all h_s reads complete

        // ---- partial exchange: reuse first 12KB of h_s ----
        {
            unsigned pa = h_base + (((unsigned)(ks * 32 + lane) * NCOL + cb) * 4u);
            sts_v2b64(pa,      acc[0], acc[1]);
            sts_v2b64(pa + 16, acc[2], acc[3]);
            sts_v2b64(pa + 32, acc[4], acc[5]);
        }
        __syncthreads();

        // ---- gate math: thread = (gb, gjj) ----
        {
            float rz = brz, rr = brr, rh = brh;
#pragma unroll
            for (int q = 0; q < 4; q++) {
                const float* pp = h_s + q * (32 * NCOL) + gb * NCOL;
                rz += pp[gjj];
                rr += pp[8 + gjj];
                rh += pp[16 + gjj];
            }
            const float z = 1.0f / (1.0f + expf(-(xz + rz)));
            const float r = 1.0f / (1.0f + expf(-(xr + rr)));
            const float hh = tanhf(xh + r * rh);
            const float hn = z * hp + (1.0f - z) * hh;
            __stcg(&out[((size_t)gb * TT + t) * HH + jloc], hn);
            if (write_hlast && t == TT - 1)
                __stcg(&hlast[(size_t)gb * HH + jloc], hn);
        }

        // ---- grid barrier ----
        if (tid == 0) {
            __threadfence();
            atomicAdd(&g_arrive, 1u);
            const unsigned target = (unsigned)(t + 1) * NCTA;
            while (*(volatile unsigned*)&g_arrive < target) { }
            __threadfence();
        }
        __syncthreads();
    }

    // ---- reset barrier state (last exiting CTA) ----
    __syncthreads();
    if (tid == 0) {
        __threadfence();
        unsigned r = atomicAdd(&g_exit, 1u);
        if (r == NCTA - 1) {
            *(volatile unsigned*)&g_arrive = 0;
            __threadfence();
            *(volatile unsigned*)&g_exit = 0;
            __threadfence();
        }
    }
}

// ---------------------------------------------------------------------------
extern "C" void kernel_launch(void* const* d_in, const int* in_sizes, int n_in,
                              void* d_out, int out_size) {
    const float* input = (const float*)d_in[0];   // [B,T,D]
    const float* kern  = (const float*)d_in[1];   // [D,3H]
    const float* U     = (const float*)d_in[2];   // [H,3H]
    const float* bias  = (const float*)d_in[3];   // [2,3H]

    float* out = (float*)d_out;
    const size_t out_elems = (size_t)BB * TT * HH;
    int write_hlast = (out_size >= (int)(out_elems + BB * HH)) ? 1 : 0;
    float* hlast = out + out_elems;

    // Phase 1: x_proj GEMM
    {
        dim3 grid((BB * TT / A_BM) * (H3 / A_BN));
        xproj_kernel<<<grid, 256>>>(input, kern, bias);
    }

    // Phase 2: persistent recurrence
    {
        static int attr_set = 0;
        if (!attr_set) {
            cudaFuncSetAttribute(gru_kernel,
                                 cudaFuncAttributeMaxDynamicSharedMemorySize,
                                 SMEM_BYTES);
            attr_set = 1;
        }
        gru_kernel<<<NCTA, 256, SMEM_BYTES>>>(U, bias, out, hlast, write_hlast);
    }
}

// round 5
// speedup vs baseline: 1.2486x; 1.2486x over previous
#include <cuda_runtime.h>
#include <cuda_bf16.h>
#include <mma.h>
#include <math.h>
#include <stdint.h>

using namespace nvcuda;

// ---------------------------------------------------------------------------
// GRU (Keras reset_after=True):  B=32, T=1024, D=1024, H=1024
//  Phase 1: x_proj = input @ kernel        (split kernels + WMMA bf16 3x-split)
//  Phase 2: recurrence (persistent FFMA kernel, 512 thr/CTA); adds both biases.
// NOTE: harness emits compute_103 PTX -> NO tcgen05/'a'-suffix features.
// ---------------------------------------------------------------------------

#define BB 32
#define TT 1024
#define DD 1024
#define HH 1024
#define H3 3072
#define BT (BB * TT)

// scratch (device globals only -- no allocation allowed)
__device__ float         g_xproj[(size_t)BT * H3];           // 402 MB (raw x@W)
__device__ __nv_bfloat16 g_Ah[(size_t)BT * DD];              // 64 MB
__device__ __nv_bfloat16 g_Al[(size_t)BT * DD];              // 64 MB
__device__ __nv_bfloat16 g_Bh[(size_t)H3 * DD];              // 6 MB  (kernel^T hi)
__device__ __nv_bfloat16 g_Bl[(size_t)H3 * DD];              // 6 MB  (kernel^T lo)

__device__ unsigned g_arrive = 0;
__device__ unsigned g_exit   = 0;

// ------------------------------ helpers ------------------------------------
__device__ __forceinline__ unsigned smaddr(const void* p) {
    return (unsigned)__cvta_generic_to_shared(p);
}
__device__ __forceinline__ unsigned long long bcast2(float x) {
    unsigned long long r;
    asm("mov.b64 %0, {%1, %1};" : "=l"(r) : "f"(x));
    return r;
}
__device__ __forceinline__ void ffma2(unsigned long long& d, unsigned long long a,
                                      unsigned long long b) {
    asm volatile("fma.rn.f32x2 %0, %1, %2, %0;" : "+l"(d) : "l"(a), "l"(b));
}
__device__ __forceinline__ void lds_v2b64(unsigned long long& a, unsigned long long& b,
                                          unsigned addr) {
    asm volatile("ld.shared.v2.b64 {%0, %1}, [%2];" : "=l"(a), "=l"(b) : "r"(addr));
}
__device__ __forceinline__ void sts_v2b64(unsigned addr, unsigned long long a,
                                          unsigned long long b) {
    asm volatile("st.shared.v2.b64 [%0], {%1, %2};" :: "r"(addr), "l"(a), "l"(b)
                 : "memory");
}
__device__ __forceinline__ void cp_async16(uint32_t saddr, const void* g) {
    asm volatile("cp.async.cg.shared.global [%0], [%1], 16;" :: "r"(saddr), "l"(g)
                 : "memory");
}
#define CP_COMMIT() asm volatile("cp.async.commit_group;" ::: "memory")
#define CP_WAIT_1() asm volatile("cp.async.wait_group 1;" ::: "memory")
#define CP_WAIT_0() asm volatile("cp.async.wait_group 0;" ::: "memory")

// single shared dynamic-smem symbol (same type in every kernel)
extern __shared__ char dynsmem[];

// ---------------------------------------------------------------------------
// Split kernels
// ---------------------------------------------------------------------------
__global__ void __launch_bounds__(256) splitA_kernel(const float* __restrict__ A) {
    size_t i = (size_t)blockIdx.x * 256 + threadIdx.x;  // float4 index
    float4 v = ((const float4*)A)[i];
    __nv_bfloat16 h0 = __float2bfloat16(v.x);
    __nv_bfloat16 h1 = __float2bfloat16(v.y);
    __nv_bfloat16 h2 = __float2bfloat16(v.z);
    __nv_bfloat16 h3 = __float2bfloat16(v.w);
    __nv_bfloat16 l0 = __float2bfloat16(v.x - __bfloat162float(h0));
    __nv_bfloat16 l1 = __float2bfloat16(v.y - __bfloat162float(h1));
    __nv_bfloat16 l2 = __float2bfloat16(v.z - __bfloat162float(h2));
    __nv_bfloat16 l3 = __float2bfloat16(v.w - __bfloat162float(h3));
    ((__nv_bfloat162*)g_Ah)[2 * i]     = __nv_bfloat162(h0, h1);
    ((__nv_bfloat162*)g_Ah)[2 * i + 1] = __nv_bfloat162(h2, h3);
    ((__nv_bfloat162*)g_Al)[2 * i]     = __nv_bfloat162(l0, l1);
    ((__nv_bfloat162*)g_Al)[2 * i + 1] = __nv_bfloat162(l2, l3);
}

// W[k][n] -> Bh/Bl[n][k] (transpose + split)
__global__ void __launch_bounds__(256) splitW_kernel(const float* __restrict__ W) {
    __shared__ float tile[32][33];
    const int n0 = blockIdx.x * 32;
    const int k0 = blockIdx.y * 32;
    const int tx = threadIdx.x & 31;
    const int ty = threadIdx.x >> 5;  // 0..7
#pragma unroll
    for (int r = 0; r < 32; r += 8)
        tile[ty + r][tx] = W[(size_t)(k0 + ty + r) * H3 + n0 + tx];
    __syncthreads();
#pragma unroll
    for (int r = 0; r < 32; r += 8) {
        int n = n0 + ty + r;
        float v = tile[tx][ty + r];
        __nv_bfloat16 hi = __float2bfloat16(v);
        __nv_bfloat16 lo = __float2bfloat16(v - __bfloat162float(hi));
        g_Bh[(size_t)n * DD + k0 + tx] = hi;
        g_Bl[(size_t)n * DD + k0 + tx] = lo;
    }
}

// ---------------------------------------------------------------------------
// x_proj WMMA kernel: C[128,128] per CTA, 256 thr (8 warps, warp tile 32x64).
// 3xBF16 split: Ah*Bh + Ah*Bl + Al*Bh, fp32 accumulation. BK=32, double buffer.
// ---------------------------------------------------------------------------
#define X_BK 32
#define X_LDT 40                                   // BK + 8 pad (bf16 elems)
#define X_MAT_ELEMS (128 * X_LDT)                  // 5120 elems per matrix tile
#define X_STAGE_ELEMS (4 * X_MAT_ELEMS)            // Ah, Al, Bh, Bl
#define X_SMEM_BYTES (2 * X_STAGE_ELEMS * 2)       // 81920 B

typedef wmma::fragment<wmma::matrix_a, 16, 16, 16, __nv_bfloat16, wmma::row_major> AFrag;
typedef wmma::fragment<wmma::matrix_b, 16, 16, 16, __nv_bfloat16, wmma::col_major> BFrag;
typedef wmma::fragment<wmma::accumulator, 16, 16, 16, float> CFrag;

__device__ __forceinline__ void xp_load_stage(__nv_bfloat16* base, int m0, int n0,
                                              int k0, int tid) {
    const __nv_bfloat16* gsrc[4] = {
        g_Ah + (size_t)m0 * DD + k0,
        g_Al + (size_t)m0 * DD + k0,
        g_Bh + (size_t)n0 * DD + k0,
        g_Bl + (size_t)n0 * DD + k0,
    };
#pragma unroll
    for (int it = 0; it < 8; it++) {
        int idx = it * 256 + tid;
        int q = idx >> 9;
        int r = (idx >> 2) & 127;
        int c = idx & 3;
        cp_async16(smaddr(base + q * X_MAT_ELEMS + r * X_LDT + c * 8),
                   gsrc[q] + (size_t)r * DD + c * 8);
    }
}

__global__ void __launch_bounds__(256) xproj_wmma_kernel() {
    __nv_bfloat16* sm = (__nv_bfloat16*)dynsmem;
    const int tid  = threadIdx.x;
    const int warp = tid >> 5;
    const int m0 = (blockIdx.x / (H3 / 128)) * 128;
    const int n0 = (blockIdx.x % (H3 / 128)) * 128;
    const int wm = warp & 3;    // row group (32 rows)
    const int wn = warp >> 2;   // col group (64 cols)

    CFrag acc[2][4];
#pragma unroll
    for (int i = 0; i < 2; i++)
#pragma unroll
        for (int j = 0; j < 4; j++) wmma::fill_fragment(acc[i][j], 0.0f);

    xp_load_stage(sm, m0, n0, 0, tid);
    CP_COMMIT();
    xp_load_stage(sm + X_STAGE_ELEMS, m0, n0, X_BK, tid);
    CP_COMMIT();

    for (int ss = 0; ss < 32; ss++) {
        const int s = ss & 1;
        if (ss == 31) { CP_WAIT_0(); } else { CP_WAIT_1(); }
        __syncthreads();

        const __nv_bfloat16* base = sm + s * X_STAGE_ELEMS;
        const __nv_bfloat16* sAh = base;
        const __nv_bfloat16* sAl = base + X_MAT_ELEMS;
        const __nv_bfloat16* sBh = base + 2 * X_MAT_ELEMS;
        const __nv_bfloat16* sBl = base + 3 * X_MAT_ELEMS;

#pragma unroll
        for (int kk = 0; kk < 2; kk++) {
            const int ko = kk * 16;
            AFrag ah[2], al[2];
            BFrag bh[4], bl[4];
#pragma unroll
            for (int i = 0; i < 2; i++) {
                wmma::load_matrix_sync(ah[i], sAh + (wm * 32 + i * 16) * X_LDT + ko, X_LDT);
                wmma::load_matrix_sync(al[i], sAl + (wm * 32 + i * 16) * X_LDT + ko, X_LDT);
            }
#pragma unroll
            for (int j = 0; j < 4; j++) {
                wmma::load_matrix_sync(bh[j], sBh + (wn * 64 + j * 16) * X_LDT + ko, X_LDT);
                wmma::load_matrix_sync(bl[j], sBl + (wn * 64 + j * 16) * X_LDT + ko, X_LDT);
            }
#pragma unroll
            for (int i = 0; i < 2; i++)
#pragma unroll
                for (int j = 0; j < 4; j++) {
                    wmma::mma_sync(acc[i][j], ah[i], bh[j], acc[i][j]);
                    wmma::mma_sync(acc[i][j], ah[i], bl[j], acc[i][j]);
                    wmma::mma_sync(acc[i][j], al[i], bh[j], acc[i][j]);
                }
        }

        __syncthreads();
        if (ss + 2 < 32) {
            xp_load_stage(sm + s * X_STAGE_ELEMS, m0, n0, (ss + 2) * X_BK, tid);
            CP_COMMIT();
        }
    }

    // epilogue: store raw product (bias folded into gru gate phase)
#pragma unroll
    for (int i = 0; i < 2; i++)
#pragma unroll
        for (int j = 0; j < 4; j++) {
            float* p = g_xproj + (size_t)(m0 + wm * 32 + i * 16) * H3 +
                       n0 + wn * 64 + j * 16;
            wmma::store_matrix_sync(p, acc[i][j], H3, wmma::mem_row_major);
        }
}

// ---------------------------------------------------------------------------
// Kernel B: persistent GRU recurrence. 128 CTAs x 512 threads.
// CTA c owns j-units [c*8, c*8+8) -> 24 gemm cols. U resident in smem.
// h layout: float4 chunks, chunk index = k4*32 + (b ^ (k4 & 31)).
// ---------------------------------------------------------------------------
#define NCTA 128
#define JB 8
#define NCOL (3 * JB)                 // 24
#define SM_H_FLOATS (HH * BB)         // 32768 floats (128 KB)
#define SM_U_FLOATS (HH * NCOL)       // 24576 floats (96 KB)
#define SMEM_BYTES ((SM_H_FLOATS + SM_U_FLOATS) * 4)
#define PART_STRIDE 28                // padded partial row (floats)

__global__ void __launch_bounds__(512, 1) gru_kernel(
    const float* __restrict__ U,    // [H, 3H]
    const float* __restrict__ bias, // [2, 3H]
    float* __restrict__ out,        // [B, T, H]
    float* __restrict__ hlast,
    int write_hlast
) {
    float* h_s = (float*)dynsmem;       // 128 KB
    float* U_s = h_s + SM_H_FLOATS;     // 96 KB  [k][24]
    float4* h_s4 = (float4*)h_s;

    const int tid  = threadIdx.x;
    const int j0   = blockIdx.x * JB;
    const int lane = tid & 31;
    const int warp = tid >> 5;          // 0..15

    // one-time U slice load
    for (int idx = tid; idx < SM_U_FLOATS; idx += 512) {
        int k = idx / NCOL;
        int m = idx % NCOL;
        int g = m >> 3;
        int jj = m & 7;
        U_s[idx] = __ldg(&U[(size_t)k * H3 + g * HH + j0 + jj]);
    }

    // gate-phase identity (tid < 256); combined biases b_in + b_rec
    const int gb   = tid & 31;
    const int gjj  = (tid >> 5) & 7;
    const int jloc = j0 + gjj;
    const float bz = __ldg(&bias[jloc])            + __ldg(&bias[H3 + jloc]);
    const float br = __ldg(&bias[HH + jloc])       + __ldg(&bias[H3 + HH + jloc]);
    const float bh = __ldg(&bias[2 * HH + jloc])   + __ldg(&bias[H3 + 2 * HH + jloc]);
    const float brh_only = __ldg(&bias[H3 + 2 * HH + jloc]);   // recurrent-side h bias
    const float binh_only = __ldg(&bias[2 * HH + jloc]);       // input-side h bias
    (void)bh;

    // gemm identity: 16 warps -> (cg 0/1, ks 0..7)
    const int cg = warp & 1;
    const int ks = warp >> 1;
    const int cb = cg * 12;

    const unsigned h_base = smaddr(h_s);
    const unsigned u_base = smaddr(U_s);

    // staging identity: b = tid>>4 (0..31), s16 = tid&15
    const int sb  = tid >> 4;
    const int s16 = tid & 15;

    for (int t = 0; t < TT; t++) {
        // ---- stage h_prev ----
        if (t == 0) {
#pragma unroll 4
            for (int i = 0; i < 16; i++) {
                int k4 = s16 + i * 16;
                h_s4[k4 * 32 + (sb ^ (k4 & 31))] = make_float4(0.f, 0.f, 0.f, 0.f);
            }
        } else {
            const float4* src = (const float4*)(out + ((size_t)sb * TT + (t - 1)) * HH);
#pragma unroll 4
            for (int i = 0; i < 16; i++) {
                int k4 = s16 + i * 16;
                float4 v = __ldcg(&src[k4]);
                h_s4[k4 * 32 + (sb ^ (k4 & 31))] = v;
            }
        }

        // prefetch x_proj (raw x@W) for gate phase
        float xz = 0.f, xr = 0.f, xh = 0.f;
        if (tid < 256) {
            const size_t xrow = ((size_t)gb * TT + t) * H3;
            xz = __ldg(&g_xproj[xrow + jloc]);
            xr = __ldg(&g_xproj[xrow + HH + jloc]);
            xh = __ldg(&g_xproj[xrow + 2 * HH + jloc]);
        }

        __syncthreads();

        // ---- GEMM: rec[b=lane][cols cb..cb+11], k in [ks*128, ks*128+128) ----
        unsigned long long acc[6];
#pragma unroll
        for (int i = 0; i < 6; i++) acc[i] = 0ull;

#pragma unroll 4
        for (int k4i = 0; k4i < 32; k4i++) {
            const int k4 = ks * 32 + k4i;
            float4 h4;
            {
                unsigned ha = h_base + (unsigned)(k4 * 512) +
                              (unsigned)((lane ^ (k4 & 31)) << 4);
                asm volatile("ld.shared.v4.f32 {%0, %1, %2, %3}, [%4];"
                             : "=f"(h4.x), "=f"(h4.y), "=f"(h4.z), "=f"(h4.w)
                             : "r"(ha));
            }
            const unsigned ub = u_base + (unsigned)(k4 * 4 * NCOL * 4) + (unsigned)(cb * 4);
#pragma unroll
            for (int j = 0; j < 4; j++) {
                float hv = (j == 0) ? h4.x : (j == 1) ? h4.y : (j == 2) ? h4.z : h4.w;
                unsigned long long h2 = bcast2(hv);
                unsigned long long w0, w1, w2, w3, w4, w5;
                unsigned ua = ub + (unsigned)(j * NCOL * 4);
                lds_v2b64(w0, w1, ua);
                lds_v2b64(w2, w3, ua + 16);
                lds_v2b64(w4, w5, ua + 32);
                ffma2(acc[0], h2, w0);
                ffma2(acc[1], h2, w1);
                ffma2(acc[2], h2, w2);
                ffma2(acc[3], h2, w3);
                ffma2(acc[4], h2, w4);
                ffma2(acc[5], h2, w5);
            }
        }

        // h_prev for gate output (read before h_s reuse)
        float hp = 0.f;
        if (tid < 256) {
            int k4 = jloc >> 2;
            const float* hc = (const float*)&h_s4[k4 * 32 + (gb ^ (k4 & 31))];
            hp = hc[jloc & 3];
        }

        __syncthreads();

        // ---- partial exchange into h_s region (stride 28 floats) ----
        {
            unsigned pa = h_base + (unsigned)((ks * 32 + lane) * PART_STRIDE * 4) +
                          (unsigned)(cb * 4);
            sts_v2b64(pa,      acc[0], acc[1]);
            sts_v2b64(pa + 16, acc[2], acc[3]);
            sts_v2b64(pa + 32, acc[4], acc[5]);
        }
        __syncthreads();

        // ---- gate math (tid < 256) ----
        if (tid < 256) {
            float rz = 0.f, rr = 0.f, rh = 0.f;
#pragma unroll
            for (int q = 0; q < 8; q++) {
                const float* pp = h_s + (q * 32 + gb) * PART_STRIDE;
                rz += pp[gjj];
                rr += pp[8 + gjj];
                rh += pp[16 + gjj];
            }
            // z = sig(xz + b_inz + rz + b_recz); r = sig(...); 
            // hh = tanh(xh + b_inh + r*(rh + b_rech))
            const float z  = 1.0f / (1.0f + expf(-(xz + rz + bz)));
            const float r  = 1.0f / (1.0f + expf(-(xr + rr + br)));
            const float hhv = tanhf(xh + binh_only + r * (rh + brh_only));
            const float hn = z * hp + (1.0f - z) * hhv;
            __stcg(&out[((size_t)gb * TT + t) * HH + jloc], hn);
            if (write_hlast && t == TT - 1)
                __stcg(&hlast[(size_t)gb * HH + jloc], hn);
        }

        // ---- grid barrier ----
        if (tid == 0) {
            __threadfence();
            atomicAdd(&g_arrive, 1u);
            const unsigned target = (unsigned)(t + 1) * NCTA;
            while (*(volatile unsigned*)&g_arrive < target) { }
            __threadfence();
        }
        __syncthreads();
    }

    // reset barrier state
    __syncthreads();
    if (tid == 0) {
        __threadfence();
        unsigned r = atomicAdd(&g_exit, 1u);
        if (r == NCTA - 1) {
            *(volatile unsigned*)&g_arrive = 0;
            __threadfence();
            *(volatile unsigned*)&g_exit = 0;
            __threadfence();
        }
    }
}

// ---------------------------------------------------------------------------
extern "C" void kernel_launch(void* const* d_in, const int* in_sizes, int n_in,
                              void* d_out, int out_size) {
    const float* input = (const float*)d_in[0];   // [B,T,D]
    const float* kern  = (const float*)d_in[1];   // [D,3H]
    const float* U     = (const float*)d_in[2];   // [H,3H]
    const float* bias  = (const float*)d_in[3];   // [2,3H]

    float* out = (float*)d_out;
    const size_t out_elems = (size_t)BB * TT * HH;
    int write_hlast = (out_size >= (int)(out_elems + BB * HH)) ? 1 : 0;
    float* hlast = out + out_elems;

    static int attr_set = 0;
    if (!attr_set) {
        cudaFuncSetAttribute(gru_kernel,
                             cudaFuncAttributeMaxDynamicSharedMemorySize, SMEM_BYTES);
        cudaFuncSetAttribute(xproj_wmma_kernel,
                             cudaFuncAttributeMaxDynamicSharedMemorySize, X_SMEM_BYTES);
        attr_set = 1;
    }

    // Phase 1a: split inputs
    splitA_kernel<<<(BT * DD / 4 + 255) / 256, 256>>>(input);
    splitW_kernel<<<dim3(H3 / 32, DD / 32), 256>>>(kern);

    // Phase 1b: x_proj via WMMA bf16 (3xBF16 split)
    xproj_wmma_kernel<<<(BT / 128) * (H3 / 128), 256, X_SMEM_BYTES>>>();

    // Phase 2: persistent recurrence (adds b_in + b_rec)
    gru_kernel<<<NCTA, 512, SMEM_BYTES>>>(U, bias, out, hlast, write_hlast);
}

// round 6
// speedup vs baseline: 2.0138x; 1.6128x over previous
#include <cuda_runtime.h>
#include <cuda_bf16.h>
#include <mma.h>
#include <math.h>
#include <stdint.h>

using namespace nvcuda;

// ---------------------------------------------------------------------------
// GRU (Keras reset_after=True):  B=32, T=1024, D=1024, H=1024
//  Phase 1: x_proj = input @ kernel   (split kernels + WMMA bf16 3x-split)
//  Phase 2: recurrence — persistent kernel, h@U on tensor pipe via
//           mma.sync.m16n8k16 bf16 with hi/lo 3x-split, fp32 accum.
// NOTE: harness emits compute_103 PTX -> NO tcgen05/'a'-suffix features.
// ---------------------------------------------------------------------------

#define BB 32
#define TT 1024
#define DD 1024
#define HH 1024
#define H3 3072
#define BT (BB * TT)

// scratch (device globals only -- no allocation allowed)
__device__ float         g_xproj[(size_t)BT * H3];           // 402 MB (raw x@W)
__device__ __nv_bfloat16 g_Ah[(size_t)BT * DD];              // 64 MB
__device__ __nv_bfloat16 g_Al[(size_t)BT * DD];              // 64 MB
__device__ __nv_bfloat16 g_Bh[(size_t)H3 * DD];              // 6 MB  (kernel^T hi)
__device__ __nv_bfloat16 g_Bl[(size_t)H3 * DD];              // 6 MB  (kernel^T lo)
// per-step h in bf16 hi/lo, layout [k=1024][b=32] each
__device__ __nv_bfloat16 g_hbf[2 * HH * BB];                 // 128 KB

__device__ unsigned g_arrive = 0;
__device__ unsigned g_exit   = 0;

// ------------------------------ helpers ------------------------------------
__device__ __forceinline__ unsigned smaddr(const void* p) {
    return (unsigned)__cvta_generic_to_shared(p);
}
__device__ __forceinline__ void cp_async16(uint32_t saddr, const void* g) {
    asm volatile("cp.async.cg.shared.global [%0], [%1], 16;" :: "r"(saddr), "l"(g)
                 : "memory");
}
#define CP_COMMIT() asm volatile("cp.async.commit_group;" ::: "memory")
#define CP_WAIT_1() asm volatile("cp.async.wait_group 1;" ::: "memory")
#define CP_WAIT_0() asm volatile("cp.async.wait_group 0;" ::: "memory")

#define LDSM_X4_T(r0, r1, r2, r3, addr) \
    asm volatile("ldmatrix.sync.aligned.m8n8.x4.trans.shared.b16 {%0,%1,%2,%3}, [%4];" \
                 : "=r"(r0), "=r"(r1), "=r"(r2), "=r"(r3) : "r"(addr))
#define LDSM_X2_T(r0, r1, addr) \
    asm volatile("ldmatrix.sync.aligned.m8n8.x2.trans.shared.b16 {%0,%1}, [%2];" \
                 : "=r"(r0), "=r"(r1) : "r"(addr))
#define MMA_BF16(d, a, b) \
    asm volatile("mma.sync.aligned.m16n8k16.row.col.f32.bf16.bf16.f32 " \
                 "{%0,%1,%2,%3}, {%4,%5,%6,%7}, {%8,%9}, {%0,%1,%2,%3};" \
                 : "+f"((d)[0]), "+f"((d)[1]), "+f"((d)[2]), "+f"((d)[3]) \
                 : "r"((a)[0]), "r"((a)[1]), "r"((a)[2]), "r"((a)[3]), \
                   "r"((b)[0]), "r"((b)[1]))

// single shared dynamic-smem symbol (same type in every kernel)
extern __shared__ char dynsmem[];

// ---------------------------------------------------------------------------
// Split kernels
// ---------------------------------------------------------------------------
__global__ void __launch_bounds__(256) splitA_kernel(const float* __restrict__ A) {
    size_t i = (size_t)blockIdx.x * 256 + threadIdx.x;  // float4 index
    float4 v = ((const float4*)A)[i];
    __nv_bfloat16 h0 = __float2bfloat16(v.x);
    __nv_bfloat16 h1 = __float2bfloat16(v.y);
    __nv_bfloat16 h2 = __float2bfloat16(v.z);
    __nv_bfloat16 h3 = __float2bfloat16(v.w);
    __nv_bfloat16 l0 = __float2bfloat16(v.x - __bfloat162float(h0));
    __nv_bfloat16 l1 = __float2bfloat16(v.y - __bfloat162float(h1));
    __nv_bfloat16 l2 = __float2bfloat16(v.z - __bfloat162float(h2));
    __nv_bfloat16 l3 = __float2bfloat16(v.w - __bfloat162float(h3));
    ((__nv_bfloat162*)g_Ah)[2 * i]     = __nv_bfloat162(h0, h1);
    ((__nv_bfloat162*)g_Ah)[2 * i + 1] = __nv_bfloat162(h2, h3);
    ((__nv_bfloat162*)g_Al)[2 * i]     = __nv_bfloat162(l0, l1);
    ((__nv_bfloat162*)g_Al)[2 * i + 1] = __nv_bfloat162(l2, l3);
}

// W[k][n] -> Bh/Bl[n][k] (transpose + split)
__global__ void __launch_bounds__(256) splitW_kernel(const float* __restrict__ W) {
    __shared__ float tile[32][33];
    const int n0 = blockIdx.x * 32;
    const int k0 = blockIdx.y * 32;
    const int tx = threadIdx.x & 31;
    const int ty = threadIdx.x >> 5;  // 0..7
#pragma unroll
    for (int r = 0; r < 32; r += 8)
        tile[ty + r][tx] = W[(size_t)(k0 + ty + r) * H3 + n0 + tx];
    __syncthreads();
#pragma unroll
    for (int r = 0; r < 32; r += 8) {
        int n = n0 + ty + r;
        float v = tile[tx][ty + r];
        __nv_bfloat16 hi = __float2bfloat16(v);
        __nv_bfloat16 lo = __float2bfloat16(v - __bfloat162float(hi));
        g_Bh[(size_t)n * DD + k0 + tx] = hi;
        g_Bl[(size_t)n * DD + k0 + tx] = lo;
    }
}

// ---------------------------------------------------------------------------
// x_proj WMMA kernel: C[128,128] per CTA, 256 thr (8 warps, warp tile 32x64).
// ---------------------------------------------------------------------------
#define X_BK 32
#define X_LDT 40
#define X_MAT_ELEMS (128 * X_LDT)
#define X_STAGE_ELEMS (4 * X_MAT_ELEMS)
#define X_SMEM_BYTES (2 * X_STAGE_ELEMS * 2)

typedef wmma::fragment<wmma::matrix_a, 16, 16, 16, __nv_bfloat16, wmma::row_major> AFrag;
typedef wmma::fragment<wmma::matrix_b, 16, 16, 16, __nv_bfloat16, wmma::col_major> BFrag;
typedef wmma::fragment<wmma::accumulator, 16, 16, 16, float> CFrag;

__device__ __forceinline__ void xp_load_stage(__nv_bfloat16* base, int m0, int n0,
                                              int k0, int tid) {
    const __nv_bfloat16* gsrc[4] = {
        g_Ah + (size_t)m0 * DD + k0,
        g_Al + (size_t)m0 * DD + k0,
        g_Bh + (size_t)n0 * DD + k0,
        g_Bl + (size_t)n0 * DD + k0,
    };
#pragma unroll
    for (int it = 0; it < 8; it++) {
        int idx = it * 256 + tid;
        int q = idx >> 9;
        int r = (idx >> 2) & 127;
        int c = idx & 3;
        cp_async16(smaddr(base + q * X_MAT_ELEMS + r * X_LDT + c * 8),
                   gsrc[q] + (size_t)r * DD + c * 8);
    }
}

__global__ void __launch_bounds__(256) xproj_wmma_kernel() {
    __nv_bfloat16* sm = (__nv_bfloat16*)dynsmem;
    const int tid  = threadIdx.x;
    const int warp = tid >> 5;
    const int m0 = (blockIdx.x / (H3 / 128)) * 128;
    const int n0 = (blockIdx.x % (H3 / 128)) * 128;
    const int wm = warp & 3;
    const int wn = warp >> 2;

    CFrag acc[2][4];
#pragma unroll
    for (int i = 0; i < 2; i++)
#pragma unroll
        for (int j = 0; j < 4; j++) wmma::fill_fragment(acc[i][j], 0.0f);

    xp_load_stage(sm, m0, n0, 0, tid);
    CP_COMMIT();
    xp_load_stage(sm + X_STAGE_ELEMS, m0, n0, X_BK, tid);
    CP_COMMIT();

    for (int ss = 0; ss < 32; ss++) {
        const int s = ss & 1;
        if (ss == 31) { CP_WAIT_0(); } else { CP_WAIT_1(); }
        __syncthreads();

        const __nv_bfloat16* base = sm + s * X_STAGE_ELEMS;
        const __nv_bfloat16* sAh = base;
        const __nv_bfloat16* sAl = base + X_MAT_ELEMS;
        const __nv_bfloat16* sBh = base + 2 * X_MAT_ELEMS;
        const __nv_bfloat16* sBl = base + 3 * X_MAT_ELEMS;

#pragma unroll
        for (int kk = 0; kk < 2; kk++) {
            const int ko = kk * 16;
            AFrag ah[2], al[2];
            BFrag bh[4], bl[4];
#pragma unroll
            for (int i = 0; i < 2; i++) {
                wmma::load_matrix_sync(ah[i], sAh + (wm * 32 + i * 16) * X_LDT + ko, X_LDT);
                wmma::load_matrix_sync(al[i], sAl + (wm * 32 + i * 16) * X_LDT + ko, X_LDT);
            }
#pragma unroll
            for (int j = 0; j < 4; j++) {
                wmma::load_matrix_sync(bh[j], sBh + (wn * 64 + j * 16) * X_LDT + ko, X_LDT);
                wmma::load_matrix_sync(bl[j], sBl + (wn * 64 + j * 16) * X_LDT + ko, X_LDT);
            }
#pragma unroll
            for (int i = 0; i < 2; i++)
#pragma unroll
                for (int j = 0; j < 4; j++) {
                    wmma::mma_sync(acc[i][j], ah[i], bh[j], acc[i][j]);
                    wmma::mma_sync(acc[i][j], ah[i], bl[j], acc[i][j]);
                    wmma::mma_sync(acc[i][j], al[i], bh[j], acc[i][j]);
                }
        }

        __syncthreads();
        if (ss + 2 < 32) {
            xp_load_stage(sm + s * X_STAGE_ELEMS, m0, n0, (ss + 2) * X_BK, tid);
            CP_COMMIT();
        }
    }

#pragma unroll
    for (int i = 0; i < 2; i++)
#pragma unroll
        for (int j = 0; j < 4; j++) {
            float* p = g_xproj + (size_t)(m0 + wm * 32 + i * 16) * H3 +
                       n0 + wn * 64 + j * 16;
            wmma::store_matrix_sync(p, acc[i][j], H3, wmma::mem_row_major);
        }
}

// ---------------------------------------------------------------------------
// Kernel B: persistent GRU recurrence, tensor-core GEMM.
// 128 CTAs x 512 threads. CTA owns 24 rec cols (8 j-units x {z,r,h}).
// smem: A (h hi|lo interleaved, SW128) 128 KB; U hi/lo bf16 [k][24] 96 KB.
// 12 mma warps: nt = w%3 (8-col tile), ks = w/3 (256-k slice).
// Partials (4 x 32 x 26 f32 = 13.3 KB) alias the A region after reads.
// ---------------------------------------------------------------------------
#define NCTA 128
#define JB 8
#define NCOL 24
#define SM_A_BYTES (HH * 128)                 // 131072: [k][128B] hi|lo chunks
#define SM_B_BYTES (HH * NCOL * 2)            // 49152 per split
#define SMEM_BYTES (SM_A_BYTES + 2 * SM_B_BYTES)   // 229376
#define PSTRIDE 26

__global__ void __launch_bounds__(512, 1) gru_kernel(
    const float* __restrict__ U,    // [H, 3H]
    const float* __restrict__ bias, // [2, 3H]
    float* __restrict__ out,        // [B, T, H]
    float* __restrict__ hlast,
    int write_hlast
) {
    char* smA = dynsmem;                                // 128 KB
    __nv_bfloat16* smBh = (__nv_bfloat16*)(dynsmem + SM_A_BYTES);
    __nv_bfloat16* smBl = (__nv_bfloat16*)(dynsmem + SM_A_BYTES + SM_B_BYTES);
    float* smP = (float*)dynsmem;                       // partials alias A

    const int tid  = threadIdx.x;
    const int j0   = blockIdx.x * JB;
    const int lane = tid & 31;
    const int warp = tid >> 5;          // 0..15

    // ---- one-time U slice load + split to bf16 hi/lo ----
    for (int idx = tid; idx < HH * NCOL; idx += 512) {
        int k = idx / NCOL;
        int n = idx % NCOL;
        int g = n >> 3;
        int jj = n & 7;
        float v = __ldg(&U[(size_t)k * H3 + g * HH + j0 + jj]);
        __nv_bfloat16 hi = __float2bfloat16(v);
        smBh[idx] = hi;
        smBl[idx] = __float2bfloat16(v - __bfloat162float(hi));
    }

    // ---- gate identity (tid < 256): thread = (b = tid&31, jj = tid>>5) ----
    const int gb   = tid & 31;
    const int gjj  = (tid >> 5) & 7;
    const int jloc = j0 + gjj;
    const float bz = __ldg(&bias[jloc])      + __ldg(&bias[H3 + jloc]);
    const float br = __ldg(&bias[HH + jloc]) + __ldg(&bias[H3 + HH + jloc]);
    const float binh = __ldg(&bias[2 * HH + jloc]);
    const float brh  = __ldg(&bias[H3 + 2 * HH + jloc]);

    // ---- mma identity ----
    const int nt = warp % 3;            // n 8-col tile (z/r/h)
    const int ks = warp / 3;            // k slice (0..3), 256 k each
    const unsigned aBase = smaddr(smA);
    const unsigned bhBase = smaddr(smBh);
    const unsigned blBase = smaddr(smBl);
    const unsigned pBase = smaddr(smP);

    // per-lane constant addressing for ldmatrix
    const int laneoffA = (lane & 7) + ((lane & 16) ? 8 : 0);  // k row offset
    const int hb = (lane >> 3) & 1;                            // chunk +1
    const unsigned swzA = (unsigned)(((lane & 7) << 4));       // xor term (k&7)*16
    const int laneoffB = (lane & 7) + ((lane & 8) ? 8 : 0);

    float hp = 0.0f;   // previous h for this gate thread (register-resident)
    unsigned step = 0;

    for (int t = 0; t < TT; t++) {
        if (t > 0) {
            // ---- stage h (bf16 hi/lo) into swizzled smem A ----
#pragma unroll
            for (int i = 0; i < 16; i++) {
                int idx = tid + i * 512;          // 0..8191
                int k = idx >> 3;
                int c = idx & 7;
                const __nv_bfloat16* src =
                    g_hbf + ((c & 4) ? (HH * BB) : 0) + k * BB + (c & 3) * 8;
                unsigned dst = aBase + (unsigned)(k * 128) +
                               (unsigned)(((c * 16) ^ ((k & 7) * 16)));
                cp_async16(dst, src);
            }
            CP_COMMIT();
        }

        // prefetch x_proj for gate phase (hidden behind gemm)
        float xz = 0.f, xr = 0.f, xh = 0.f;
        if (tid < 256) {
            const size_t xrow = ((size_t)gb * TT + t) * H3;
            xz = __ldg(&g_xproj[xrow + jloc]);
            xr = __ldg(&g_xproj[xrow + HH + jloc]);
            xh = __ldg(&g_xproj[xrow + 2 * HH + jloc]);
        }

        if (t > 0) {
            CP_WAIT_0();
            __syncthreads();

            float acc0[4] = {0.f, 0.f, 0.f, 0.f};   // m rows 0-15
            float acc1[4] = {0.f, 0.f, 0.f, 0.f};   // m rows 16-31

            if (warp < 12) {
                // A chunk bases: hi-m0 = chunks 0/1, hi-m1 = 2/3, lo-m0 = 4/5, lo-m1 = 6/7
                unsigned rowA = aBase + (unsigned)((ks * 256 + laneoffA) * 128);
                unsigned aH0 = rowA + ((unsigned)((0 + hb) * 16) ^ swzA);
                unsigned aH1 = rowA + ((unsigned)((2 + hb) * 16) ^ swzA);
                unsigned aL0 = rowA + ((unsigned)((4 + hb) * 16) ^ swzA);
                unsigned aL1 = rowA + ((unsigned)((6 + hb) * 16) ^ swzA);
                unsigned bH = bhBase + (unsigned)((ks * 256 + laneoffB) * (NCOL * 2) + nt * 16);
                unsigned bL = blBase + (unsigned)((ks * 256 + laneoffB) * (NCOL * 2) + nt * 16);

#pragma unroll 4
                for (int kt = 0; kt < 16; kt++) {
                    uint32_t ah0[4], ah1[4], al0[4], al1[4], fbh[2], fbl[2];
                    LDSM_X4_T(ah0[0], ah0[1], ah0[2], ah0[3], aH0);
                    LDSM_X4_T(ah1[0], ah1[1], ah1[2], ah1[3], aH1);
                    LDSM_X4_T(al0[0], al0[1], al0[2], al0[3], aL0);
                    LDSM_X4_T(al1[0], al1[1], al1[2], al1[3], aL1);
                    LDSM_X2_T(fbh[0], fbh[1], bH);
                    LDSM_X2_T(fbl[0], fbl[1], bL);
                    MMA_BF16(acc0, ah0, fbh);
                    MMA_BF16(acc0, ah0, fbl);
                    MMA_BF16(acc0, al0, fbh);
                    MMA_BF16(acc1, ah1, fbh);
                    MMA_BF16(acc1, ah1, fbl);
                    MMA_BF16(acc1, al1, fbh);
                    aH0 += 16 * 128; aH1 += 16 * 128;
                    aL0 += 16 * 128; aL1 += 16 * 128;
                    bH += 16 * (NCOL * 2); bL += 16 * (NCOL * 2);
                }
            }

            __syncthreads();   // all A reads complete before partials alias A

            if (warp < 12) {
                const int r = lane >> 2;
                const int c = (lane & 3) * 2;
                const int n = nt * 8 + c;
                // m rows: r, r+8 (acc0 tile m0-15); r+16, r+24 (acc1 tile m16-31)
                unsigned p0 = pBase + (unsigned)(((ks * 32 + r) * PSTRIDE + n) * 4);
                unsigned p1 = pBase + (unsigned)(((ks * 32 + r + 8) * PSTRIDE + n) * 4);
                unsigned p2 = pBase + (unsigned)(((ks * 32 + r + 16) * PSTRIDE + n) * 4);
                unsigned p3 = pBase + (unsigned)(((ks * 32 + r + 24) * PSTRIDE + n) * 4);
                asm volatile("st.shared.v2.f32 [%0], {%1, %2};" :: "r"(p0), "f"(acc0[0]), "f"(acc0[1]) : "memory");
                asm volatile("st.shared.v2.f32 [%0], {%1, %2};" :: "r"(p1), "f"(acc0[2]), "f"(acc0[3]) : "memory");
                asm volatile("st.shared.v2.f32 [%0], {%1, %2};" :: "r"(p2), "f"(acc1[0]), "f"(acc1[1]) : "memory");
                asm volatile("st.shared.v2.f32 [%0], {%1, %2};" :: "r"(p3), "f"(acc1[2]), "f"(acc1[3]) : "memory");
            }
            __syncthreads();
        }

        // ---- gate math (tid < 256) ----
        if (tid < 256) {
            float rz = 0.f, rr = 0.f, rh = 0.f;
            if (t > 0) {
#pragma unroll
                for (int q = 0; q < 4; q++) {
                    const float* pp = smP + (q * 32 + gb) * PSTRIDE;
                    rz += pp[gjj];
                    rr += pp[8 + gjj];
                    rh += pp[16 + gjj];
                }
            }
            const float z   = 1.0f / (1.0f + expf(-(xz + rz + bz)));
            const float r   = 1.0f / (1.0f + expf(-(xr + rr + br)));
            const float hhv = tanhf(xh + binh + r * (rh + brh));
            const float hn  = z * hp + (1.0f - z) * hhv;
            hp = hn;
            __stcg(&out[((size_t)gb * TT + t) * HH + jloc], hn);
            if (write_hlast && t == TT - 1)
                __stcg(&hlast[(size_t)gb * HH + jloc], hn);
            // emit bf16 hi/lo for next step's GEMM
            __nv_bfloat16 hi = __float2bfloat16(hn);
            __nv_bfloat16 lo = __float2bfloat16(hn - __bfloat162float(hi));
            g_hbf[jloc * BB + gb] = hi;
            g_hbf[HH * BB + jloc * BB + gb] = lo;
        }

        // ---- grid barrier (orders g_hbf writes for all CTAs) ----
        step++;
        if (tid == 0) {
            __threadfence();
            atomicAdd(&g_arrive, 1u);
            const unsigned target = step * NCTA;
            while (*(volatile unsigned*)&g_arrive < target) { }
            __threadfence();
        }
        __syncthreads();
    }

    // ---- reset barrier state (last exiting CTA) for graph replay ----
    __syncthreads();
    if (tid == 0) {
        __threadfence();
        unsigned r = atomicAdd(&g_exit, 1u);
        if (r == NCTA - 1) {
            *(volatile unsigned*)&g_arrive = 0;
            __threadfence();
            *(volatile unsigned*)&g_exit = 0;
            __threadfence();
        }
    }
}

// ---------------------------------------------------------------------------
extern "C" void kernel_launch(void* const* d_in, const int* in_sizes, int n_in,
                              void* d_out, int out_size) {
    const float* input = (const float*)d_in[0];   // [B,T,D]
    const float* kern  = (const float*)d_in[1];   // [D,3H]
    const float* U     = (const float*)d_in[2];   // [H,3H]
    const float* bias  = (const float*)d_in[3];   // [2,3H]

    float* out = (float*)d_out;
    const size_t out_elems = (size_t)BB * TT * HH;
    int write_hlast = (out_size >= (int)(out_elems + BB * HH)) ? 1 : 0;
    float* hlast = out + out_elems;

    static int attr_set = 0;
    if (!attr_set) {
        cudaFuncSetAttribute(gru_kernel,
                             cudaFuncAttributeMaxDynamicSharedMemorySize, SMEM_BYTES);
        cudaFuncSetAttribute(xproj_wmma_kernel,
                             cudaFuncAttributeMaxDynamicSharedMemorySize, X_SMEM_BYTES);
        attr_set = 1;
    }

    // Phase 1a: split inputs
    splitA_kernel<<<(BT * DD / 4 + 255) / 256, 256>>>(input);
    splitW_kernel<<<dim3(H3 / 32, DD / 32), 256>>>(kern);

    // Phase 1b: x_proj via WMMA bf16 (3xBF16 split)
    xproj_wmma_kernel<<<(BT / 128) * (H3 / 128), 256, X_SMEM_BYTES>>>();

    // Phase 2: persistent recurrence (tensor-core h@U)
    gru_kernel<<<NCTA, 512, SMEM_BYTES>>>(U, bias, out, hlast, write_hlast);
}